// round 5
// baseline (speedup 1.0000x reference)
#include <cuda_runtime.h>
#include <math.h>

#define T_SEQ 2048
#define H     768
#define H3    2304
#define NL    10
#define NIN   384
#define NOUT  384

#define SCAN_BLOCKS 48
#define NW 16                // warps per scan CTA; one h element per warp

// ---------------- scratch (no allocation allowed) ----------------
__device__ float g_gi[T_SEQ * H3];     // input projections, current layer
__device__ float g_hbuf0[T_SEQ * H];   // ping-pong layer outputs (GEMM inputs)
__device__ float g_hbuf1[T_SEQ * H];
// fused {tag(hi32), h bits(lo32)} packets; 2 parity buffers; each producer CTA
// owns one 128B line (16 words) per buffer
__device__ __align__(128) unsigned long long g_pack[2][SCAN_BLOCKS * NW];

// zero packet tags at END of launch so graph replays start clean
__global__ void reset_pack_kernel() {
    const int n = 2 * SCAN_BLOCKS * NW;
    for (int i = threadIdx.x; i < n; i += blockDim.x)
        ((unsigned long long*)g_pack)[i] = 0ull;
}

// ---------------- GEMM: C[M,N] = A[M,K] * B[N,K]^T + bias[N] ----------------
__global__ void __launch_bounds__(256) gemm_nt_bias_kernel(
    const float* __restrict__ A, const float* __restrict__ B,
    const float* __restrict__ bias, float* __restrict__ C,
    int M, int N, int K)
{
    __shared__ float As[8][128];
    __shared__ float Bs[8][132];

    const int tid = threadIdx.x;
    const int bm = blockIdx.y * 128;
    const int bn = blockIdx.x * 128;
    const int m0 = (tid >> 4) * 8;
    const int n0 = (tid & 15) * 8;

    float acc[8][8];
#pragma unroll
    for (int i = 0; i < 8; i++)
#pragma unroll
        for (int j = 0; j < 8; j++) acc[i][j] = 0.f;

    const int arow = tid >> 1;
    const int akk  = (tid & 1) * 4;
    const float* Aptr = A + (size_t)(bm + arow) * K + akk;
    const float* Bptr = B + (size_t)(bn + arow) * K + akk;

    for (int k0 = 0; k0 < K; k0 += 8) {
        float4 av = *(const float4*)(Aptr + k0);
        float4 bv = *(const float4*)(Bptr + k0);
        __syncthreads();
        As[akk + 0][arow] = av.x; As[akk + 1][arow] = av.y;
        As[akk + 2][arow] = av.z; As[akk + 3][arow] = av.w;
        Bs[akk + 0][arow] = bv.x; Bs[akk + 1][arow] = bv.y;
        Bs[akk + 2][arow] = bv.z; Bs[akk + 3][arow] = bv.w;
        __syncthreads();
#pragma unroll
        for (int k = 0; k < 8; k++) {
            float4 a0 = *(const float4*)&As[k][m0];
            float4 a1 = *(const float4*)&As[k][m0 + 4];
            float4 b0 = *(const float4*)&Bs[k][n0];
            float4 b1 = *(const float4*)&Bs[k][n0 + 4];
            float ra[8] = {a0.x, a0.y, a0.z, a0.w, a1.x, a1.y, a1.z, a1.w};
            float rb[8] = {b0.x, b0.y, b0.z, b0.w, b1.x, b1.y, b1.z, b1.w};
#pragma unroll
            for (int i = 0; i < 8; i++)
#pragma unroll
                for (int j = 0; j < 8; j++)
                    acc[i][j] = fmaf(ra[i], rb[j], acc[i][j]);
        }
    }

#pragma unroll
    for (int i = 0; i < 8; i++) {
        const int row = bm + m0 + i;
#pragma unroll
        for (int j = 0; j < 8; j++)
            C[(size_t)row * N + bn + n0 + j] = acc[i][j] + bias[bn + n0 + j];
    }
}

// ---------------- GRU recurrent scan (persistent, fused single-hop handoff) -
// 48 CTAs x 512 threads. Warp w of block b owns h index j = b*16 + w.
// Producer (lane0 of each warp): ONE st.release.gpu.u64 {tag, h} -- nothing
//   precedes it, so no store-drain stall; hout STG happens after (off-path).
// Consumer: threads 0..47 each poll one producer CTA's 128B line (16 fused
//   words, MLP=16). Data arrives IN the polled words -> no second hop.
// Packets double-buffered by step parity (overwrite-race free).
__global__ void __launch_bounds__(512, 1) gru_scan_kernel(
    const float* __restrict__ gi, const float* __restrict__ w_hh,
    const float* __restrict__ b_hh, float* __restrict__ hout,
    unsigned int base)   // = layer * T_SEQ
{
    __shared__ float hs[2][H];
    const int tid  = threadIdx.x;
    const int warp = tid >> 5;
    const int lane = tid & 31;
    const int j = blockIdx.x * NW + warp;

    // preload recurrent weights into registers (24 cols/lane per gate)
    float wr0[24], wr1[24], wr2[24];
#pragma unroll
    for (int k6 = 0; k6 < 6; k6++) {
        const int c = k6 * 128 + lane * 4;
        float4 v0 = *(const float4*)(w_hh + (size_t)(0 * H + j) * H + c);
        float4 v1 = *(const float4*)(w_hh + (size_t)(1 * H + j) * H + c);
        float4 v2 = *(const float4*)(w_hh + (size_t)(2 * H + j) * H + c);
        wr0[k6*4+0] = v0.x; wr0[k6*4+1] = v0.y; wr0[k6*4+2] = v0.z; wr0[k6*4+3] = v0.w;
        wr1[k6*4+0] = v1.x; wr1[k6*4+1] = v1.y; wr1[k6*4+2] = v1.z; wr1[k6*4+3] = v1.w;
        wr2[k6*4+0] = v2.x; wr2[k6*4+1] = v2.y; wr2[k6*4+2] = v2.z; wr2[k6*4+3] = v2.w;
    }
    const float bh0 = b_hh[j];
    const float bh1 = b_hh[H + j];
    const float bh2 = b_hh[2 * H + j];

    // gi prefetched one step ahead (lane0 only)
    float c_r = 0.f, c_z = 0.f, c_n = 0.f;
    float n_r = 0.f, n_z = 0.f, n_n = 0.f;
    if (lane == 0) {
        c_r = gi[j]; c_z = gi[H + j]; c_n = gi[2 * H + j];
    }

    for (int t = 0; t < T_SEQ; t++) {
        const int buf = t & 1;           // packets of step t go to buffer t&1

        // issue next step's gi loads now; they land during poll/compute
        if (lane == 0 && (t + 1) < T_SEQ) {
            const float* g = gi + (size_t)(t + 1) * H3;
            n_r = g[j]; n_z = g[H + j]; n_n = g[2 * H + j];
        }

        float hv[24];
        float hprev = 0.f;
        if (t == 0) {
#pragma unroll
            for (int k = 0; k < 24; k++) hv[k] = 0.f;
        } else {
            const int rbuf = (t - 1) & 1;
            // threads 0..47: poll producer CTA tid's 16 fused words
            if (tid < SCAN_BLOCKS) {
                const unsigned target = base + (unsigned)t;  // tag of step t-1
                const unsigned long long* src = &g_pack[rbuf][tid * NW];
                float* dst = &hs[rbuf][tid * NW];
                unsigned pend = 0xFFFFu;
                do {
#pragma unroll
                    for (int k = 0; k < NW; k++) {
                        if (pend & (1u << k)) {
                            unsigned long long v;
                            asm volatile("ld.acquire.gpu.global.u64 %0, [%1];"
                                         : "=l"(v) : "l"(src + k));
                            if ((unsigned)(v >> 32) == target) {
                                dst[k] = __uint_as_float((unsigned)v);
                                pend &= ~(1u << k);
                            }
                        }
                    }
                } while (pend);
            }
            __syncthreads();
#pragma unroll
            for (int k6 = 0; k6 < 6; k6++) {
                float4 v = *(const float4*)(&hs[rbuf][k6 * 128 + lane * 4]);
                hv[k6*4+0] = v.x; hv[k6*4+1] = v.y; hv[k6*4+2] = v.z; hv[k6*4+3] = v.w;
            }
            if (lane == 0) hprev = hs[rbuf][j];
        }

        // three dot products of length 768, split 24 per lane
        float a0 = 0.f, a1 = 0.f, a2 = 0.f;
#pragma unroll
        for (int k = 0; k < 24; k++) {
            a0 = fmaf(wr0[k], hv[k], a0);
            a1 = fmaf(wr1[k], hv[k], a1);
            a2 = fmaf(wr2[k], hv[k], a2);
        }
#pragma unroll
        for (int off = 16; off > 0; off >>= 1) {
            a0 += __shfl_down_sync(0xffffffffu, a0, off);
            a1 += __shfl_down_sync(0xffffffffu, a1, off);
            a2 += __shfl_down_sync(0xffffffffu, a2, off);
        }

        if (lane == 0) {
            const float ghr = a0 + bh0;
            const float ghz = a1 + bh1;
            const float ghn = a2 + bh2;
            const float r = 1.f / (1.f + __expf(-(c_r + ghr)));
            const float z = 1.f / (1.f + __expf(-(c_z + ghz)));
            const float n = tanhf(c_n + r * ghn);
            const float hnew = (1.f - z) * n + z * hprev;

            // publish FIRST: single release store, no prior stores to drain
            const unsigned long long pkt =
                ((unsigned long long)(base + (unsigned)t + 1u) << 32) |
                (unsigned long long)__float_as_uint(hnew);
            asm volatile("st.release.gpu.global.u64 [%0], %1;"
                         :: "l"(&g_pack[buf][blockIdx.x * NW + warp]), "l"(pkt)
                         : "memory");

            // off-critical-path: row for the next layer's GEMM
            hout[(size_t)t * H + j] = hnew;

            // rotate prefetched gi
            c_r = n_r; c_z = n_z; c_n = n_n;
        }
    }
}

// ---------------- launch ----------------
extern "C" void kernel_launch(void* const* d_in, const int* in_sizes, int n_in,
                              void* d_out, int out_size)
{
    const float* x    = (const float*)d_in[0];
    const float* wih0 = (const float*)d_in[1];
    const float* whh0 = (const float*)d_in[2];
    const float* bih0 = (const float*)d_in[3];
    const float* bhh0 = (const float*)d_in[4];
    const float* wih  = (const float*)d_in[5];
    const float* whh  = (const float*)d_in[6];
    const float* bih  = (const float*)d_in[7];
    const float* bhh  = (const float*)d_in[8];
    const float* fcw  = (const float*)d_in[9];
    const float* fcb  = (const float*)d_in[10];

    float *gi, *hb0, *hb1;
    cudaGetSymbolAddress((void**)&gi,  g_gi);
    cudaGetSymbolAddress((void**)&hb0, g_hbuf0);
    cudaGetSymbolAddress((void**)&hb1, g_hbuf1);
    float* hb[2] = {hb0, hb1};

    const float* cur = x;
    for (int l = 0; l < NL; l++) {
        const float* wih_l = (l == 0) ? wih0 : wih + (size_t)(l - 1) * H3 * H;
        const float* whh_l = (l == 0) ? whh0 : whh + (size_t)(l - 1) * H3 * H;
        const float* bih_l = (l == 0) ? bih0 : bih + (size_t)(l - 1) * H3;
        const float* bhh_l = (l == 0) ? bhh0 : bhh + (size_t)(l - 1) * H3;
        const int K = (l == 0) ? NIN : H;

        dim3 grid_gi(H3 / 128, T_SEQ / 128);
        gemm_nt_bias_kernel<<<grid_gi, 256>>>(cur, wih_l, bih_l, gi, T_SEQ, H3, K);

        float* ho = hb[l & 1];
        gru_scan_kernel<<<SCAN_BLOCKS, 512>>>(gi, whh_l, bhh_l, ho,
                                              (unsigned)(l * T_SEQ));
        cur = ho;
    }

    dim3 grid_fc(NOUT / 128, T_SEQ / 128);
    gemm_nt_bias_kernel<<<grid_fc, 256>>>(cur, fcw, fcb, (float*)d_out,
                                          T_SEQ, NOUT, H);

    // reset packet tags so the next graph replay starts clean
    reset_pack_kernel<<<1, 256>>>();
}

// round 6
// speedup vs baseline: 2.9706x; 2.9706x over previous
#include <cuda_runtime.h>
#include <math.h>

#define T_SEQ 2048
#define H     768
#define H3    2304
#define NL    10
#define NIN   384
#define NOUT  384

#define SCAN_BLOCKS 96
#define HPB 8                 // h elements per scan CTA (8 warps, 1 each)
#define CANARY 0x7FC0DEADu    // quiet-NaN payload; unreachable by GRU math

// ---------------- scratch (no allocation allowed) ----------------
__device__ float g_gi[T_SEQ * H3];          // input projections, current layer
__device__ float g_hl[NL][T_SEQ][H];        // per-layer h outputs (canary-filled)

// fill h buffers with canary at launch START (before any scan runs);
// after a full launch the buffers hold real values, so the next replay's
// reset restores the precondition.
__global__ void reset_canary_kernel() {
    unsigned* p = (unsigned*)g_hl;
    const size_t n = (size_t)NL * T_SEQ * H;
    for (size_t i = blockIdx.x * blockDim.x + threadIdx.x; i < n;
         i += (size_t)gridDim.x * blockDim.x)
        p[i] = CANARY;
}

// ---------------- GEMM: C[M,N] = A[M,K] * B[N,K]^T + bias[N] ----------------
__global__ void __launch_bounds__(256) gemm_nt_bias_kernel(
    const float* __restrict__ A, const float* __restrict__ B,
    const float* __restrict__ bias, float* __restrict__ C,
    int M, int N, int K)
{
    __shared__ float As[8][128];
    __shared__ float Bs[8][132];

    const int tid = threadIdx.x;
    const int bm = blockIdx.y * 128;
    const int bn = blockIdx.x * 128;
    const int m0 = (tid >> 4) * 8;
    const int n0 = (tid & 15) * 8;

    float acc[8][8];
#pragma unroll
    for (int i = 0; i < 8; i++)
#pragma unroll
        for (int j = 0; j < 8; j++) acc[i][j] = 0.f;

    const int arow = tid >> 1;
    const int akk  = (tid & 1) * 4;
    const float* Aptr = A + (size_t)(bm + arow) * K + akk;
    const float* Bptr = B + (size_t)(bn + arow) * K + akk;

    for (int k0 = 0; k0 < K; k0 += 8) {
        float4 av = *(const float4*)(Aptr + k0);
        float4 bv = *(const float4*)(Bptr + k0);
        __syncthreads();
        As[akk + 0][arow] = av.x; As[akk + 1][arow] = av.y;
        As[akk + 2][arow] = av.z; As[akk + 3][arow] = av.w;
        Bs[akk + 0][arow] = bv.x; Bs[akk + 1][arow] = bv.y;
        Bs[akk + 2][arow] = bv.z; Bs[akk + 3][arow] = bv.w;
        __syncthreads();
#pragma unroll
        for (int k = 0; k < 8; k++) {
            float4 a0 = *(const float4*)&As[k][m0];
            float4 a1 = *(const float4*)&As[k][m0 + 4];
            float4 b0 = *(const float4*)&Bs[k][n0];
            float4 b1 = *(const float4*)&Bs[k][n0 + 4];
            float ra[8] = {a0.x, a0.y, a0.z, a0.w, a1.x, a1.y, a1.z, a1.w};
            float rb[8] = {b0.x, b0.y, b0.z, b0.w, b1.x, b1.y, b1.z, b1.w};
#pragma unroll
            for (int i = 0; i < 8; i++)
#pragma unroll
                for (int j = 0; j < 8; j++)
                    acc[i][j] = fmaf(ra[i], rb[j], acc[i][j]);
        }
    }

#pragma unroll
    for (int i = 0; i < 8; i++) {
        const int row = bm + m0 + i;
#pragma unroll
        for (int j = 0; j < 8; j++)
            C[(size_t)row * N + bn + n0 + j] = acc[i][j] + bias[bn + n0 + j];
    }
}

// ---------------- GRU recurrent scan (canary handoff, single store) ---------
// 96 CTAs x 256 threads. Warp w of block b owns h index j = b*8 + w.
// Producer: lane0's ONE st.relaxed.gpu.u32 of h_t[j] is simultaneously the
//   notification, the broadcast payload, and the next-GEMM input row.
// Consumer: thread tid polls words {tid, tid+256, tid+512} of row t-1 until
//   != CANARY, stages into parity-buffered smem; one __syncthreads per step.
__global__ void __launch_bounds__(256, 1) gru_scan_kernel(
    const float* __restrict__ gi, const float* __restrict__ w_hh,
    const float* __restrict__ b_hh, float* __restrict__ hl)
{
    __shared__ float hs[2][H];
    const int tid  = threadIdx.x;
    const int warp = tid >> 5;
    const int lane = tid & 31;
    const int j = blockIdx.x * HPB + warp;

    // preload recurrent weights into registers (24 cols/lane per gate)
    float wr0[24], wr1[24], wr2[24];
#pragma unroll
    for (int k6 = 0; k6 < 6; k6++) {
        const int c = k6 * 128 + lane * 4;
        float4 v0 = *(const float4*)(w_hh + (size_t)(0 * H + j) * H + c);
        float4 v1 = *(const float4*)(w_hh + (size_t)(1 * H + j) * H + c);
        float4 v2 = *(const float4*)(w_hh + (size_t)(2 * H + j) * H + c);
        wr0[k6*4+0] = v0.x; wr0[k6*4+1] = v0.y; wr0[k6*4+2] = v0.z; wr0[k6*4+3] = v0.w;
        wr1[k6*4+0] = v1.x; wr1[k6*4+1] = v1.y; wr1[k6*4+2] = v1.z; wr1[k6*4+3] = v1.w;
        wr2[k6*4+0] = v2.x; wr2[k6*4+1] = v2.y; wr2[k6*4+2] = v2.z; wr2[k6*4+3] = v2.w;
    }
    const float bh0 = b_hh[j];
    const float bh1 = b_hh[H + j];
    const float bh2 = b_hh[2 * H + j];

    for (int t = 0; t < T_SEQ; t++) {
        // gi loads issue before the poll; latency hides under it
        float gir = 0.f, giz = 0.f, gin = 0.f;
        if (lane == 0) {
            const float* g = gi + (size_t)t * H3;
            gir = g[j];
            giz = g[H + j];
            gin = g[2 * H + j];
        }

        float hv[24];
        float hprev = 0.f;
        if (t == 0) {
#pragma unroll
            for (int k = 0; k < 24; k++) hv[k] = 0.f;
        } else {
            const int rb = (t - 1) & 1;
            // poll the data itself: 3 words per thread, relaxed 32-bit loads
            {
                const unsigned* src =
                    (const unsigned*)(hl + (size_t)(t - 1) * H);
                float* dst = hs[rb];
                const int p0 = tid, p1 = tid + 256, p2 = tid + 512;
                unsigned v;
                bool d0 = false, d1 = false, d2 = false;
                do {
                    if (!d0) {
                        asm volatile("ld.relaxed.gpu.global.u32 %0, [%1];"
                                     : "=r"(v) : "l"(src + p0));
                        if (v != CANARY) { dst[p0] = __uint_as_float(v); d0 = true; }
                    }
                    if (!d1) {
                        asm volatile("ld.relaxed.gpu.global.u32 %0, [%1];"
                                     : "=r"(v) : "l"(src + p1));
                        if (v != CANARY) { dst[p1] = __uint_as_float(v); d1 = true; }
                    }
                    if (!d2) {
                        asm volatile("ld.relaxed.gpu.global.u32 %0, [%1];"
                                     : "=r"(v) : "l"(src + p2));
                        if (v != CANARY) { dst[p2] = __uint_as_float(v); d2 = true; }
                    }
                } while (!(d0 && d1 && d2));
            }
            __syncthreads();   // hs[rb] fully staged; also fences buffer reuse
#pragma unroll
            for (int k6 = 0; k6 < 6; k6++) {
                float4 v = *(const float4*)(&hs[rb][k6 * 128 + lane * 4]);
                hv[k6*4+0] = v.x; hv[k6*4+1] = v.y; hv[k6*4+2] = v.z; hv[k6*4+3] = v.w;
            }
            if (lane == 0) hprev = hs[rb][j];
        }

        // three dot products of length 768, split 24 per lane
        float a0 = 0.f, a1 = 0.f, a2 = 0.f;
#pragma unroll
        for (int k = 0; k < 24; k++) {
            a0 = fmaf(wr0[k], hv[k], a0);
            a1 = fmaf(wr1[k], hv[k], a1);
            a2 = fmaf(wr2[k], hv[k], a2);
        }
#pragma unroll
        for (int off = 16; off > 0; off >>= 1) {
            a0 += __shfl_down_sync(0xffffffffu, a0, off);
            a1 += __shfl_down_sync(0xffffffffu, a1, off);
            a2 += __shfl_down_sync(0xffffffffu, a2, off);
        }

        if (lane == 0) {
            const float ghr = a0 + bh0;
            const float ghz = a1 + bh1;
            const float ghn = a2 + bh2;
            const float r = 1.f / (1.f + __expf(-(gir + ghr)));
            const float z = 1.f / (1.f + __expf(-(giz + ghz)));
            const float n = tanhf(gin + r * ghn);
            const float hnew = (1.f - z) * n + z * hprev;

            // the ONE store: publication + broadcast + GEMM input, no drain
            asm volatile("st.relaxed.gpu.global.u32 [%0], %1;"
                         :: "l"(hl + (size_t)t * H + j),
                            "r"(__float_as_uint(hnew)) : "memory");
        }
    }
}

// ---------------- launch ----------------
extern "C" void kernel_launch(void* const* d_in, const int* in_sizes, int n_in,
                              void* d_out, int out_size)
{
    const float* x    = (const float*)d_in[0];
    const float* wih0 = (const float*)d_in[1];
    const float* whh0 = (const float*)d_in[2];
    const float* bih0 = (const float*)d_in[3];
    const float* bhh0 = (const float*)d_in[4];
    const float* wih  = (const float*)d_in[5];
    const float* whh  = (const float*)d_in[6];
    const float* bih  = (const float*)d_in[7];
    const float* bhh  = (const float*)d_in[8];
    const float* fcw  = (const float*)d_in[9];
    const float* fcb  = (const float*)d_in[10];

    float *gi, *hl;
    cudaGetSymbolAddress((void**)&gi, g_gi);
    cudaGetSymbolAddress((void**)&hl, g_hl);

    // precondition: all h slots = canary (start of every replayed graph)
    reset_canary_kernel<<<1024, 256>>>();

    const float* cur = x;
    for (int l = 0; l < NL; l++) {
        const float* wih_l = (l == 0) ? wih0 : wih + (size_t)(l - 1) * H3 * H;
        const float* whh_l = (l == 0) ? whh0 : whh + (size_t)(l - 1) * H3 * H;
        const float* bih_l = (l == 0) ? bih0 : bih + (size_t)(l - 1) * H3;
        const float* bhh_l = (l == 0) ? bhh0 : bhh + (size_t)(l - 1) * H3;
        const int K = (l == 0) ? NIN : H;

        dim3 grid_gi(H3 / 128, T_SEQ / 128);
        gemm_nt_bias_kernel<<<grid_gi, 256>>>(cur, wih_l, bih_l, gi, T_SEQ, H3, K);

        float* hl_l = hl + (size_t)l * T_SEQ * H;
        gru_scan_kernel<<<SCAN_BLOCKS, 256>>>(gi, whh_l, bhh_l, hl_l);
        cur = hl_l;
    }

    dim3 grid_fc(NOUT / 128, T_SEQ / 128);
    gemm_nt_bias_kernel<<<grid_fc, 256>>>(cur, fcw, fcb, (float*)d_out,
                                          T_SEQ, NOUT, H);
}